// round 5
// baseline (speedup 1.0000x reference)
#include <cuda_runtime.h>
#include <cuda_bf16.h>

#define L 2048
#define LMASK 2047
#define LSHIFT 11
#define PAIRMASK 0x5A48u
#define CAP 192            // finish smem-cache capacity

// ---------------- device scratch ----------------
__device__ float d_C[(size_t)L * L];          // compacted active x active matrix
__device__ unsigned long long d_best[2][L];   // ping-pong best buffers
__device__ int d_cls[L];
__device__ int d_act[L];                      // global ids of survivors of round 1 (ascending)
__device__ int d_nAct;
__device__ int d_lact[2][L];                  // ping-pong local-id lists
__device__ int d_nL[2];

__device__ __forceinline__ unsigned long long pack_g(float s, int a, int b) {
    unsigned k = (unsigned)(a * L + b);
    return ((unsigned long long)__float_as_uint(s) << 32) | (unsigned long long)(~k);
}
__device__ __forceinline__ unsigned long long pack_l(float s, int lo, int hi) {
    unsigned k = ((unsigned)lo << LSHIFT) | (unsigned)hi;
    return ((unsigned long long)__float_as_uint(s) << 32) | (unsigned long long)(~k);
}
__device__ __forceinline__ unsigned long long warp_max(unsigned long long m) {
    #pragma unroll
    for (int o = 16; o; o >>= 1) {
        unsigned long long q = __shfl_xor_sync(0xFFFFFFFFu, m, o);
        if (q > m) m = q;
    }
    return m;
}
// triangular block map: k -> (bi, bj) with bi <= bj
__device__ __forceinline__ void tri_map(int k, int& bi, int& bj) {
    int b = (int)((__fsqrt_rn(8.0f * (float)k + 1.0f) - 1.0f) * 0.5f);
    while (b * (b + 1) / 2 > k) b--;
    while ((b + 1) * (b + 2) / 2 <= k) b++;
    bj = b;
    bi = k - b * (b + 1) / 2;
}

// ---------------- K1: classes + clear best[0] ----------------
__global__ void kern_cls(const float* __restrict__ feat) {
    int i = blockIdx.x * blockDim.x + threadIdx.x;
    if (i >= L) return;
    float f0 = feat[(size_t)i * L];
    float f1 = feat[(size_t)L * L + (size_t)i * L];
    float f2 = feat[2 * (size_t)L * L + (size_t)i * L];
    float f3 = feat[3 * (size_t)L * L + (size_t)i * L];
    int c = 0; float m = f0;
    if (f1 > m) { m = f1; c = 1; }
    if (f2 > m) { m = f2; c = 2; }
    if (f3 > m) { m = f3; c = 3; }
    d_cls[i] = c;
    d_best[0][i] = 0ULL;
}

// ---------------- K2: round-1 best + zero output (triangular grid) ----------------
__global__ void kern_build(const float* __restrict__ con, float* __restrict__ out) {
    int bi, bj; tri_map(blockIdx.x, bi, bj);      // bi <= bj

    __shared__ float sB[32][33];
    __shared__ int clsR[32], clsC[32];

    int tx = threadIdx.x, ty = threadIdx.y;
    int i = bi * 32 + ty;
    int j = bj * 32 + tx;

    if (ty == 0) { clsR[tx] = d_cls[bi * 32 + tx]; clsC[tx] = d_cls[bj * 32 + tx]; }

    float a = con[(size_t)i * L + j];
    sB[ty][tx] = con[(size_t)(bj * 32 + ty) * L + (bi * 32 + tx)];
    __syncthreads();

    float b = sB[tx][ty];          // con[j][i]
    float v = 0.5f * (a + b);
    int d = j - i;
    bool band = (d >= 4) || (d <= -4);
    bool pm = (PAIRMASK >> ((clsR[ty] << 2) | clsC[tx])) & 1u;
    float s = (band && pm) ? v : 0.0f;

    out[(size_t)i * L + j] = 0.0f;
    out[(size_t)(bj * 32 + ty) * L + (bi * 32 + tx)] = 0.0f;

    // row max (vertex i): pairs (i, j) with j > i
    unsigned long long p = (s > 0.0f && j > i) ? pack_g(s, i, j) : 0ULL;
    unsigned long long m = warp_max(p);
    if (tx == 0 && m) atomicMax(&d_best[0][i], m);

    // transpose s via sB reuse, recompute priority for column reduction
    __syncthreads();
    sB[ty][tx] = s;
    __syncthreads();
    float s2 = sB[tx][ty];                 // pair (i2 = bi*32+tx, j2 = bj*32+ty)
    int i2 = bi * 32 + tx, j2 = bj * 32 + ty;
    unsigned long long p2 = (s2 > 0.0f && j2 > i2) ? pack_g(s2, i2, j2) : 0ULL;
    unsigned long long cm = warp_max(p2);
    if (tx == 0 && cm) atomicMax(&d_best[0][j2], cm);
}

// ---------------- K3: round-1 take, build d_act, clear best[0] ----------------
__global__ void kern_take1(float* __restrict__ out) {
    __shared__ int wsum[32];
    __shared__ int sTotal;
    int t = threadIdx.x;
    int lane = t & 31, wid = t >> 5;

    int f[2]; int vv[2];
    #pragma unroll
    for (int r = 0; r < 2; r++) {
        int v = 2 * t + r;
        int fl = 0;
        unsigned long long b = d_best[0][v];
        if (b) {
            unsigned k = ~((unsigned)b);
            int i = (int)(k >> LSHIFT), j = (int)(k & LMASK);
            int u = (v == i) ? j : i;
            if (d_best[0][u] == b) {
                if (v == i) {
                    float val = __uint_as_float((unsigned)(b >> 32));
                    out[i * L + j] = val;
                    out[j * L + i] = val;
                }
            } else fl = 1;
        }
        f[r] = fl; vv[r] = v;
    }

    int sum = f[0] + f[1];
    int x = sum;
    #pragma unroll
    for (int o = 1; o < 32; o <<= 1) { int y = __shfl_up_sync(0xFFFFFFFFu, x, o); if (lane >= o) x += y; }
    if (lane == 31) wsum[wid] = x;
    __syncthreads();
    if (wid == 0) {
        int z = wsum[lane];
        #pragma unroll
        for (int o = 1; o < 32; o <<= 1) { int y = __shfl_up_sync(0xFFFFFFFFu, z, o); if (lane >= o) z += y; }
        wsum[lane] = z;
        if (lane == 31) sTotal = z;
    }
    __syncthreads();
    int ex = (wid ? wsum[wid - 1] : 0) + x - sum;
    if (f[0]) d_act[ex] = vv[0];
    if (f[1]) d_act[ex + f[0]] = vv[1];
    if (t == 0) d_nAct = sTotal;

    // clear for compact's local atomicMax (all reads above precede the barriers)
    d_best[0][2 * t] = 0ULL;
    d_best[0][2 * t + 1] = 0ULL;
}

// ---------------- K4: tiled gather of C + fused round-2 best (triangular grid) ----------------
__global__ void kern_compact(const float* __restrict__ con) {
    int n = d_nAct;
    int bi, bj; tri_map(blockIdx.x, bi, bj);      // bi <= bj
    if (bi * 32 >= n || bj * 32 >= n) return;
    int ns = (n + 31) & ~31;

    __shared__ float sT[32][33];
    __shared__ int gA[32], gB[32], cA[32], cB[32];

    int tx = threadIdx.x, ty = threadIdx.y;
    if (ty == 0) {
        int a = bi * 32 + tx;
        int va = (a < n) ? d_act[a] : -1;
        gA[tx] = va; cA[tx] = (va >= 0) ? d_cls[va] : 0;
        int b = bj * 32 + tx;
        int vb = (b < n) ? d_act[b] : -1;
        gB[tx] = vb; cB[tx] = (vb >= 0) ? d_cls[vb] : 0;
    }
    __syncthreads();

    int va = gA[ty], vb = gB[tx];
    float x = (va >= 0 && vb >= 0) ? con[(size_t)va * L + vb] : 0.0f;
    int vy = gB[ty], vxa = gA[tx];
    sT[ty][tx] = (vy >= 0 && vxa >= 0) ? con[(size_t)vy * L + vxa] : 0.0f;
    __syncthreads();

    float v = 0.5f * (x + sT[tx][ty]);
    int a = bi * 32 + ty, b = bj * 32 + tx;
    float s = 0.0f;
    if (va >= 0 && vb >= 0) {
        int d = va - vb;
        bool band = (d >= 4) || (d <= -4);
        bool pm = (PAIRMASK >> ((cA[ty] << 2) | cB[tx])) & 1u;
        s = (band && pm) ? v : 0.0f;
    }
    if (a < n && b < n) d_C[(size_t)a * ns + b] = s;

    // row max (local a): pairs (a, b) with b > a
    unsigned long long p = (s > 0.0f && b > a) ? pack_l(s, a, b) : 0ULL;
    unsigned long long m = warp_max(p);
    if (tx == 0 && m) atomicMax(&d_best[0][a], m);

    // transpose via sT reuse: write mirrored tile + column reduction
    __syncthreads();
    sT[ty][tx] = s;
    __syncthreads();
    float s2 = sT[tx][ty];                 // pair (a2 = bi*32+tx, b2 = bj*32+ty)
    int a2 = bi * 32 + tx, b2 = bj * 32 + ty;
    if (b2 < n && a2 < n) d_C[(size_t)b2 * ns + a2] = s2;    // coalesced over tx
    unsigned long long p2 = (s2 > 0.0f && b2 > a2) ? pack_l(s2, a2, b2) : 0ULL;
    unsigned long long cm = warp_max(p2);
    if (tx == 0 && cm) atomicMax(&d_best[0][b2], cm);
}

// ---------------- K5: fused take + best (multi-CTA, ping-pong best buffers) ----------------
// Every block computes the take redundantly (smem); only block 0 writes out/lists.
__global__ void kern_round(int srcSel, int dstSel, int bsrc, int bdst, float* __restrict__ out) {
    __shared__ int sList[L];
    __shared__ int sNew[L];
    __shared__ int wsum[32];
    __shared__ int sTotal;

    int t = threadIdx.x, lane = t & 31, wid = t >> 5;
    int n = (srcSel < 0) ? d_nAct : d_nL[srcSel];
    if (n == 0) { if (blockIdx.x == 0 && t == 0) d_nL[dstSel] = 0; return; }
    int ns = (d_nAct + 31) & ~31;
    const int* lst = (srcSel < 0) ? 0 : d_lact[srcSel];
    for (int x = t; x < n; x += 1024) sList[x] = lst ? lst[x] : x;
    __syncthreads();

    // ---- take (reads d_best[bsrc] only) ----
    int f[2]; int vv[2];
    #pragma unroll
    for (int r = 0; r < 2; r++) {
        int idx = 2 * t + r;
        int fl = 0, la = -1;
        if (idx < n) {
            la = sList[idx];
            unsigned long long b = d_best[bsrc][la];
            if (b) {
                unsigned k = ~((unsigned)b);
                int lo = (int)(k >> LSHIFT), hi = (int)(k & LMASK);
                int lu = (la == lo) ? hi : lo;
                if (d_best[bsrc][lu] == b) {
                    if (la == lo && blockIdx.x == 0) {
                        float val = __uint_as_float((unsigned)(b >> 32));
                        int gi = d_act[lo], gj = d_act[hi];
                        out[gi * L + gj] = val;
                        out[gj * L + gi] = val;
                    }
                } else fl = 1;
            }
        }
        f[r] = fl; vv[r] = la;
    }

    int sum = f[0] + f[1];
    int x = sum;
    #pragma unroll
    for (int o = 1; o < 32; o <<= 1) { int y = __shfl_up_sync(0xFFFFFFFFu, x, o); if (lane >= o) x += y; }
    if (lane == 31) wsum[wid] = x;
    __syncthreads();
    if (wid == 0) {
        int z = wsum[lane];
        #pragma unroll
        for (int o = 1; o < 32; o <<= 1) { int y = __shfl_up_sync(0xFFFFFFFFu, z, o); if (lane >= o) z += y; }
        wsum[lane] = z;
        if (lane == 31) sTotal = z;
    }
    __syncthreads();
    int ex = (wid ? wsum[wid - 1] : 0) + x - sum;
    if (f[0]) sNew[ex] = vv[0];
    if (f[1]) sNew[ex + f[0]] = vv[1];
    if (blockIdx.x == 0) {
        if (f[0]) d_lact[dstSel][ex] = vv[0];
        if (f[1]) d_lact[dstSel][ex + f[0]] = vv[1];
        if (t == 0) d_nL[dstSel] = sTotal;
    }
    __syncthreads();
    int nn = sTotal;

    // ---- best over new list (writes d_best[bdst] only) ----
    int gw = blockIdx.x * 32 + wid, tw = gridDim.x * 32;
    for (int a = gw; a < nn; a += tw) {
        int la = sNew[a];
        const float* __restrict__ row = d_C + (size_t)la * ns;
        unsigned long long m = 0ULL;
        for (int l = lane; l < nn; l += 32) {
            int lb = sNew[l];
            float s = row[lb];
            if (s > 0.0f) {
                unsigned long long p = (la < lb) ? pack_l(s, la, lb) : pack_l(s, lb, la);
                if (p > m) m = p;
            }
        }
        m = warp_max(m);
        if (lane == 0) d_best[bdst][la] = m;
    }
}

// ---------------- K6: persistent tail with smem-cached C submatrix ----------------
__global__ void kern_finish(int sel, int bsel, float* __restrict__ out) {
    extern __shared__ float sC[];              // CAP*CAP floats (dynamic)
    __shared__ int sG[L];
    __shared__ int sCur[L];
    __shared__ int sTmp[L];
    __shared__ int sPos[L];
    __shared__ unsigned long long sBest[L];
    __shared__ int wsum[32];
    __shared__ int sTotal;

    int t = threadIdx.x, lane = t & 31, wid = t >> 5;
    int n = d_nL[sel];
    if (n == 0) return;
    int n0 = d_nAct;
    int ns = (n0 + 31) & ~31;

    for (int x = t; x < n; x += 1024) {
        int la = d_lact[sel][x];
        sCur[x] = la;
        sPos[la] = x;
        sBest[la] = d_best[bsel][la];
        sG[la] = d_act[la];
    }
    __syncthreads();

    bool useC = (n <= CAP);
    int ne = n;
    if (useC) {
        for (int idx = t; idx < ne * ne; idx += 1024) {
            int ai = idx / ne, bi2 = idx - ai * ne;
            sC[idx] = d_C[(size_t)sCur[ai] * ns + sCur[bi2]];
        }
        __syncthreads();
    }

    while (n > 0) {
        // ---- take ----
        int f[2]; int vv[2];
        #pragma unroll
        for (int r = 0; r < 2; r++) {
            int idx = 2 * t + r;
            int fl = 0, la = -1;
            if (idx < n) {
                la = sCur[idx];
                unsigned long long b = sBest[la];
                if (b) {
                    unsigned k = ~((unsigned)b);
                    int lo = (int)(k >> LSHIFT), hi = (int)(k & LMASK);
                    int lu = (la == lo) ? hi : lo;
                    if (sBest[lu] == b) {
                        if (la == lo) {
                            float val = __uint_as_float((unsigned)(b >> 32));
                            int gi = sG[lo], gj = sG[hi];
                            out[gi * L + gj] = val;
                            out[gj * L + gi] = val;
                        }
                    } else fl = 1;
                }
            }
            f[r] = fl; vv[r] = la;
        }

        int sum = f[0] + f[1];
        int x = sum;
        #pragma unroll
        for (int o = 1; o < 32; o <<= 1) { int y = __shfl_up_sync(0xFFFFFFFFu, x, o); if (lane >= o) x += y; }
        if (lane == 31) wsum[wid] = x;
        __syncthreads();
        if (wid == 0) {
            int z = wsum[lane];
            #pragma unroll
            for (int o = 1; o < 32; o <<= 1) { int y = __shfl_up_sync(0xFFFFFFFFu, z, o); if (lane >= o) z += y; }
            wsum[lane] = z;
            if (lane == 31) sTotal = z;
        }
        __syncthreads();
        int ex = (wid ? wsum[wid - 1] : 0) + x - sum;
        if (f[0]) sTmp[ex] = vv[0];
        if (f[1]) sTmp[ex + f[0]] = vv[1];
        __syncthreads();
        int nn = sTotal;
        for (int x2 = t; x2 < nn; x2 += 1024) sCur[x2] = sTmp[x2];
        __syncthreads();
        n = nn;
        if (n == 0) break;

        // ---- best ----
        for (int ai = wid; ai < n; ai += 32) {
            int la = sCur[ai];
            int pa = sPos[la];
            unsigned long long m = 0ULL;
            for (int li = lane; li < n; li += 32) {
                int lb = sCur[li];
                float s = useC ? sC[pa * ne + sPos[lb]]
                               : d_C[(size_t)la * ns + lb];
                if (s > 0.0f) {
                    unsigned long long p = (la < lb) ? pack_l(s, la, lb) : pack_l(s, lb, la);
                    if (p > m) m = p;
                }
            }
            m = warp_max(m);
            if (lane == 0) sBest[la] = m;
        }
        __syncthreads();
    }
}

// ---------------- launch ----------------
extern "C" void kernel_launch(void* const* d_in, const int* in_sizes, int n_in,
                              void* d_out, int out_size) {
    const float* con  = (const float*)d_in[0];
    const float* feat = (const float*)d_in[1];
    if (n_in >= 2 && in_sizes[0] > in_sizes[1]) {
        const float* tmp = con; con = feat; feat = tmp;
    }
    float* out = (float*)d_out;

    cudaFuncSetAttribute(kern_finish, cudaFuncAttributeMaxDynamicSharedMemorySize,
                         CAP * CAP * (int)sizeof(float));

    const int TRI = (L / 32) * (L / 32 + 1) / 2;   // 2080
    dim3 tb(32, 32);

    kern_cls<<<8, 256>>>(feat);
    kern_build<<<TRI, tb>>>(con, out);             // round-1 best + output zeroing
    kern_take1<<<1, 1024>>>(out);                  // -> d_act, clears best[0]
    kern_compact<<<TRI, tb>>>(con);                // C gather + round-2 best -> best[0]

    kern_round<<<64, 1024>>>(-1, 0, 0, 1, out);    // take2 -> list0, best3 -> buf1
    kern_round<<<64, 1024>>>(0, 1, 1, 0, out);     // take3 -> list1, best4 -> buf0
    kern_round<<<64, 1024>>>(1, 0, 0, 1, out);     // take4 -> list0, best5 -> buf1

    kern_finish<<<1, 1024, CAP * CAP * (int)sizeof(float)>>>(0, 1, out);
}

// round 6
// speedup vs baseline: 1.2895x; 1.2895x over previous
#include <cuda_runtime.h>
#include <cuda_bf16.h>

#define L 2048
#define LMASK 2047
#define LSHIFT 11
#define PAIRMASK 0x5A48u
#define CAP 192            // finish smem-cache capacity

// ---------------- device scratch ----------------
__device__ float d_C[(size_t)L * L];          // compacted active x active matrix
__device__ unsigned long long d_best[L];      // per-vertex / per-local-row best priority
__device__ int d_cls[L];
__device__ int d_act[L];                      // global ids of round-1 survivors (ascending)
__device__ int d_nAct;
__device__ int d_lact[2][L];                  // ping-pong local-id lists
__device__ int d_nL[2];

__device__ __forceinline__ unsigned long long pack_g(float s, int a, int b) {
    unsigned k = (unsigned)(a * L + b);
    return ((unsigned long long)__float_as_uint(s) << 32) | (unsigned long long)(~k);
}
__device__ __forceinline__ unsigned long long pack_l(float s, int lo, int hi) {
    unsigned k = ((unsigned)lo << LSHIFT) | (unsigned)hi;
    return ((unsigned long long)__float_as_uint(s) << 32) | (unsigned long long)(~k);
}
__device__ __forceinline__ unsigned long long warp_max(unsigned long long m) {
    #pragma unroll
    for (int o = 16; o; o >>= 1) {
        unsigned long long q = __shfl_xor_sync(0xFFFFFFFFu, m, o);
        if (q > m) m = q;
    }
    return m;
}
// triangular block map: k -> (bi, bj) with bi <= bj
__device__ __forceinline__ void tri_map(int k, int& bi, int& bj) {
    int b = (int)((__fsqrt_rn(8.0f * (float)k + 1.0f) - 1.0f) * 0.5f);
    while (b * (b + 1) / 2 > k) b--;
    while ((b + 1) * (b + 2) / 2 <= k) b++;
    bj = b;
    bi = k - b * (b + 1) / 2;
}

// ---------------- K1: classes + clear best ----------------
__global__ void kern_cls(const float* __restrict__ feat) {
    int i = blockIdx.x * blockDim.x + threadIdx.x;
    if (i >= L) return;
    float f0 = feat[(size_t)i * L];
    float f1 = feat[(size_t)L * L + (size_t)i * L];
    float f2 = feat[2 * (size_t)L * L + (size_t)i * L];
    float f3 = feat[3 * (size_t)L * L + (size_t)i * L];
    int c = 0; float m = f0;
    if (f1 > m) { m = f1; c = 1; }
    if (f2 > m) { m = f2; c = 2; }
    if (f3 > m) { m = f3; c = 3; }
    d_cls[i] = c;
    d_best[i] = 0ULL;
}

// ---------------- K2: round-1 best + zero output (triangular grid) ----------------
__global__ void kern_build(const float* __restrict__ con, float* __restrict__ out) {
    int bi, bj; tri_map(blockIdx.x, bi, bj);      // bi <= bj

    __shared__ float sB[32][33];
    __shared__ int clsR[32], clsC[32];

    int tx = threadIdx.x, ty = threadIdx.y;
    int i = bi * 32 + ty;
    int j = bj * 32 + tx;

    if (ty == 0) { clsR[tx] = d_cls[bi * 32 + tx]; clsC[tx] = d_cls[bj * 32 + tx]; }

    float a = con[(size_t)i * L + j];
    sB[ty][tx] = con[(size_t)(bj * 32 + ty) * L + (bi * 32 + tx)];
    __syncthreads();

    float b = sB[tx][ty];          // con[j][i]
    float v = 0.5f * (a + b);
    int d = j - i;
    bool band = (d >= 4) || (d <= -4);
    bool pm = (PAIRMASK >> ((clsR[ty] << 2) | clsC[tx])) & 1u;
    float s = (band && pm) ? v : 0.0f;

    out[(size_t)i * L + j] = 0.0f;
    out[(size_t)(bj * 32 + ty) * L + (bi * 32 + tx)] = 0.0f;

    // row max (vertex i): pairs (i, j) with j > i
    unsigned long long p = (s > 0.0f && j > i) ? pack_g(s, i, j) : 0ULL;
    unsigned long long m = warp_max(p);
    if (tx == 0 && m) atomicMax(&d_best[i], m);

    // transpose s via sB reuse; recompute priority for column reduction
    __syncthreads();
    sB[ty][tx] = s;
    __syncthreads();
    float s2 = sB[tx][ty];                 // pair (i2 = bi*32+tx, j2 = bj*32+ty)
    int i2 = bi * 32 + tx, j2 = bj * 32 + ty;
    unsigned long long p2 = (s2 > 0.0f && j2 > i2) ? pack_g(s2, i2, j2) : 0ULL;
    unsigned long long cm = warp_max(p2);
    if (tx == 0 && cm) atomicMax(&d_best[j2], cm);
}

// ---------------- K3: round-1 take, build d_act, clear best ----------------
__global__ void kern_take1(float* __restrict__ out) {
    __shared__ int wsum[32];
    __shared__ int sTotal;
    int t = threadIdx.x;
    int lane = t & 31, wid = t >> 5;

    int f[2]; int vv[2];
    #pragma unroll
    for (int r = 0; r < 2; r++) {
        int v = 2 * t + r;
        int fl = 0;
        unsigned long long b = d_best[v];
        if (b) {
            unsigned k = ~((unsigned)b);
            int i = (int)(k >> LSHIFT), j = (int)(k & LMASK);
            int u = (v == i) ? j : i;
            if (d_best[u] == b) {
                if (v == i) {
                    float val = __uint_as_float((unsigned)(b >> 32));
                    out[i * L + j] = val;
                    out[j * L + i] = val;
                }
            } else fl = 1;
        }
        f[r] = fl; vv[r] = v;
    }

    int sum = f[0] + f[1];
    int x = sum;
    #pragma unroll
    for (int o = 1; o < 32; o <<= 1) { int y = __shfl_up_sync(0xFFFFFFFFu, x, o); if (lane >= o) x += y; }
    if (lane == 31) wsum[wid] = x;
    __syncthreads();
    if (wid == 0) {
        int z = wsum[lane];
        #pragma unroll
        for (int o = 1; o < 32; o <<= 1) { int y = __shfl_up_sync(0xFFFFFFFFu, z, o); if (lane >= o) z += y; }
        wsum[lane] = z;
        if (lane == 31) sTotal = z;
    }
    __syncthreads();
    int ex = (wid ? wsum[wid - 1] : 0) + x - sum;
    if (f[0]) d_act[ex] = vv[0];
    if (f[1]) d_act[ex + f[0]] = vv[1];
    if (t == 0) d_nAct = sTotal;

    // clear for compact's local atomicMax (all d_best reads are above)
    d_best[2 * t] = 0ULL;
    d_best[2 * t + 1] = 0ULL;
}

// ---------------- K4: tiled gather of C + fused round-2 best (triangular grid) ----------------
__global__ void kern_compact(const float* __restrict__ con) {
    int n = d_nAct;
    int bi, bj; tri_map(blockIdx.x, bi, bj);      // bi <= bj
    if (bi * 32 >= n || bj * 32 >= n) return;
    int ns = (n + 31) & ~31;

    __shared__ float sT[32][33];
    __shared__ int gA[32], gB[32], cA[32], cB[32];

    int tx = threadIdx.x, ty = threadIdx.y;
    if (ty == 0) {
        int a = bi * 32 + tx;
        int va = (a < n) ? d_act[a] : -1;
        gA[tx] = va; cA[tx] = (va >= 0) ? d_cls[va] : 0;
        int b = bj * 32 + tx;
        int vb = (b < n) ? d_act[b] : -1;
        gB[tx] = vb; cB[tx] = (vb >= 0) ? d_cls[vb] : 0;
    }
    __syncthreads();

    int va = gA[ty], vb = gB[tx];
    float x = (va >= 0 && vb >= 0) ? con[(size_t)va * L + vb] : 0.0f;
    int vy = gB[ty], vxa = gA[tx];
    sT[ty][tx] = (vy >= 0 && vxa >= 0) ? con[(size_t)vy * L + vxa] : 0.0f;
    __syncthreads();

    float v = 0.5f * (x + sT[tx][ty]);
    int a = bi * 32 + ty, b = bj * 32 + tx;
    float s = 0.0f;
    if (va >= 0 && vb >= 0) {
        int d = va - vb;
        bool band = (d >= 4) || (d <= -4);
        bool pm = (PAIRMASK >> ((cA[ty] << 2) | cB[tx])) & 1u;
        s = (band && pm) ? v : 0.0f;
    }
    if (a < n && b < n) d_C[(size_t)a * ns + b] = s;

    // row max (local a): pairs (a, b) with b > a
    unsigned long long p = (s > 0.0f && b > a) ? pack_l(s, a, b) : 0ULL;
    unsigned long long m = warp_max(p);
    if (tx == 0 && m) atomicMax(&d_best[a], m);

    // transpose via sT reuse: mirrored tile write + column reduction
    __syncthreads();
    sT[ty][tx] = s;
    __syncthreads();
    float s2 = sT[tx][ty];                 // pair (a2 = bi*32+tx, b2 = bj*32+ty)
    int a2 = bi * 32 + tx, b2 = bj * 32 + ty;
    if (b2 < n && a2 < n) d_C[(size_t)b2 * ns + a2] = s2;    // coalesced over tx
    unsigned long long p2 = (s2 > 0.0f && b2 > a2) ? pack_l(s2, a2, b2) : 0ULL;
    unsigned long long cm = warp_max(p2);
    if (tx == 0 && cm) atomicMax(&d_best[b2], cm);
}

// ---------------- K5: local-space take (1 block) ----------------
// srcSel < 0: identity list 0..d_nAct
__global__ void kern_takeL(int srcSel, int dstSel, float* __restrict__ out) {
    __shared__ int wsum[32];
    __shared__ int sTotal;
    int t = threadIdx.x;
    int lane = t & 31, wid = t >> 5;
    int n = (srcSel < 0) ? d_nAct : d_nL[srcSel];
    const int* lst = (srcSel < 0) ? 0 : d_lact[srcSel];

    int f[2]; int vv[2];
    #pragma unroll
    for (int r = 0; r < 2; r++) {
        int idx = 2 * t + r;
        int fl = 0, la = -1;
        if (idx < n) {
            la = lst ? lst[idx] : idx;
            unsigned long long b = d_best[la];
            if (b) {
                unsigned k = ~((unsigned)b);
                int lo = (int)(k >> LSHIFT), hi = (int)(k & LMASK);
                int lu = (la == lo) ? hi : lo;
                if (d_best[lu] == b) {
                    if (la == lo) {
                        float val = __uint_as_float((unsigned)(b >> 32));
                        int gi = d_act[lo], gj = d_act[hi];
                        out[gi * L + gj] = val;
                        out[gj * L + gi] = val;
                    }
                } else fl = 1;
            }
        }
        f[r] = fl; vv[r] = la;
    }

    int sum = f[0] + f[1];
    int x = sum;
    #pragma unroll
    for (int o = 1; o < 32; o <<= 1) { int y = __shfl_up_sync(0xFFFFFFFFu, x, o); if (lane >= o) x += y; }
    if (lane == 31) wsum[wid] = x;
    __syncthreads();
    if (wid == 0) {
        int z = wsum[lane];
        #pragma unroll
        for (int o = 1; o < 32; o <<= 1) { int y = __shfl_up_sync(0xFFFFFFFFu, z, o); if (lane >= o) z += y; }
        wsum[lane] = z;
        if (lane == 31) sTotal = z;
    }
    __syncthreads();
    int ex = (wid ? wsum[wid - 1] : 0) + x - sum;
    if (f[0]) d_lact[dstSel][ex] = vv[0];
    if (f[1]) d_lact[dstSel][ex + f[0]] = vv[1];
    if (t == 0) d_nL[dstSel] = sTotal;
}

// ---------------- K6: local-space best over C (multi-CTA, warp per row) ----------------
__global__ void kern_bestL(int sel) {
    __shared__ int sAct[L];
    int n = d_nL[sel];
    if (n == 0) return;
    int ns = (d_nAct + 31) & ~31;
    const int* lst = d_lact[sel];
    for (int t = threadIdx.x; t < n; t += blockDim.x) sAct[t] = lst[t];
    __syncthreads();

    int lane = threadIdx.x & 31;
    int gw = (blockIdx.x * blockDim.x + threadIdx.x) >> 5;
    int tw = (gridDim.x * blockDim.x) >> 5;

    for (int a = gw; a < n; a += tw) {
        int la = sAct[a];
        const float* __restrict__ row = d_C + (size_t)la * ns;
        unsigned long long m = 0ULL;
        for (int l = lane; l < n; l += 32) {
            int lb = sAct[l];
            float s = row[lb];
            if (s > 0.0f) {
                unsigned long long p = (la < lb) ? pack_l(s, la, lb) : pack_l(s, lb, la);
                if (p > m) m = p;
            }
        }
        m = warp_max(m);
        if (lane == 0) d_best[la] = m;
    }
}

// ---------------- K7: persistent tail with smem-cached C submatrix ----------------
__global__ void kern_finish(int sel, float* __restrict__ out) {
    extern __shared__ float sC[];              // CAP*CAP floats (dynamic)
    __shared__ int sG[L];
    __shared__ int sCur[L];
    __shared__ int sTmp[L];
    __shared__ int sPos[L];
    __shared__ unsigned long long sBest[L];
    __shared__ int wsum[32];
    __shared__ int sTotal;

    int t = threadIdx.x, lane = t & 31, wid = t >> 5;
    int n = d_nL[sel];
    if (n == 0) return;
    int n0 = d_nAct;
    int ns = (n0 + 31) & ~31;

    for (int x = t; x < n; x += 1024) {
        int la = d_lact[sel][x];
        sCur[x] = la;
        sPos[la] = x;
        sBest[la] = d_best[la];
        sG[la] = d_act[la];
    }
    __syncthreads();

    bool useC = (n <= CAP);
    int ne = n;
    if (useC) {
        for (int idx = t; idx < ne * ne; idx += 1024) {
            int ai = idx / ne, bi2 = idx - ai * ne;
            sC[idx] = d_C[(size_t)sCur[ai] * ns + sCur[bi2]];
        }
        __syncthreads();
    }

    while (n > 0) {
        // ---- take ----
        int f[2]; int vv[2];
        #pragma unroll
        for (int r = 0; r < 2; r++) {
            int idx = 2 * t + r;
            int fl = 0, la = -1;
            if (idx < n) {
                la = sCur[idx];
                unsigned long long b = sBest[la];
                if (b) {
                    unsigned k = ~((unsigned)b);
                    int lo = (int)(k >> LSHIFT), hi = (int)(k & LMASK);
                    int lu = (la == lo) ? hi : lo;
                    if (sBest[lu] == b) {
                        if (la == lo) {
                            float val = __uint_as_float((unsigned)(b >> 32));
                            int gi = sG[lo], gj = sG[hi];
                            out[gi * L + gj] = val;
                            out[gj * L + gi] = val;
                        }
                    } else fl = 1;
                }
            }
            f[r] = fl; vv[r] = la;
        }

        int sum = f[0] + f[1];
        int x = sum;
        #pragma unroll
        for (int o = 1; o < 32; o <<= 1) { int y = __shfl_up_sync(0xFFFFFFFFu, x, o); if (lane >= o) x += y; }
        if (lane == 31) wsum[wid] = x;
        __syncthreads();
        if (wid == 0) {
            int z = wsum[lane];
            #pragma unroll
            for (int o = 1; o < 32; o <<= 1) { int y = __shfl_up_sync(0xFFFFFFFFu, z, o); if (lane >= o) z += y; }
            wsum[lane] = z;
            if (lane == 31) sTotal = z;
        }
        __syncthreads();
        int ex = (wid ? wsum[wid - 1] : 0) + x - sum;
        if (f[0]) sTmp[ex] = vv[0];
        if (f[1]) sTmp[ex + f[0]] = vv[1];
        __syncthreads();
        int nn = sTotal;
        for (int x2 = t; x2 < nn; x2 += 1024) sCur[x2] = sTmp[x2];
        __syncthreads();
        n = nn;
        if (n == 0) break;

        // ---- best ----
        for (int ai = wid; ai < n; ai += 32) {
            int la = sCur[ai];
            int pa = sPos[la];
            unsigned long long m = 0ULL;
            for (int li = lane; li < n; li += 32) {
                int lb = sCur[li];
                float s = useC ? sC[pa * ne + sPos[lb]]
                               : d_C[(size_t)la * ns + lb];
                if (s > 0.0f) {
                    unsigned long long p = (la < lb) ? pack_l(s, la, lb) : pack_l(s, lb, la);
                    if (p > m) m = p;
                }
            }
            m = warp_max(m);
            if (lane == 0) sBest[la] = m;
        }
        __syncthreads();
    }
}

// ---------------- launch ----------------
extern "C" void kernel_launch(void* const* d_in, const int* in_sizes, int n_in,
                              void* d_out, int out_size) {
    const float* con  = (const float*)d_in[0];
    const float* feat = (const float*)d_in[1];
    if (n_in >= 2 && in_sizes[0] > in_sizes[1]) {
        const float* tmp = con; con = feat; feat = tmp;
    }
    float* out = (float*)d_out;

    static int smemSet = 0;
    if (!smemSet) {
        cudaFuncSetAttribute(kern_finish, cudaFuncAttributeMaxDynamicSharedMemorySize,
                             CAP * CAP * (int)sizeof(float));
        smemSet = 1;
    }

    const int TRI = (L / 32) * (L / 32 + 1) / 2;   // 2080
    dim3 tb(32, 32);

    kern_cls<<<8, 256>>>(feat);
    kern_build<<<TRI, tb>>>(con, out);             // round-1 best + output zeroing
    kern_take1<<<1, 1024>>>(out);                  // -> d_act, clears d_best
    kern_compact<<<TRI, tb>>>(con);                // C gather + round-2 best

    kern_takeL<<<1, 1024>>>(-1, 0, out);           // take round 2
    kern_bestL<<<64, 1024>>>(0);                   // best round 3
    kern_takeL<<<1, 1024>>>(0, 1, out);            // take round 3
    kern_bestL<<<64, 1024>>>(1);                   // best round 4
    kern_takeL<<<1, 1024>>>(1, 0, out);            // take round 4
    kern_bestL<<<64, 1024>>>(0);                   // best round 5
    kern_takeL<<<1, 1024>>>(0, 1, out);            // take round 5
    kern_bestL<<<64, 1024>>>(1);                   // best round 6

    kern_finish<<<1, 1024, CAP * CAP * (int)sizeof(float)>>>(1, out);  // tail (n small)
}